// round 2
// baseline (speedup 1.0000x reference)
#include <cuda_runtime.h>
#include <math_constants.h>

// ---------------- problem constants ----------------
#define N_NODES 100000
#define N_EDGES 1600000
#define DIM_IN  128
#define DIM_HID 128
#define DIM_OUT 64
#define NEG_SLOPE 0.2f

// ---------------- scratch (device globals; no allocation allowed) ----------
__device__ float g_h1[(size_t)N_NODES * DIM_HID];   // x @ W1_src
__device__ float g_acc[(size_t)N_NODES * DIM_HID];  // layer1 aggregate -> h (after finalize)
__device__ float g_h2[(size_t)N_NODES * DIM_OUT];   // h @ W2_src
__device__ float g_logit[N_EDGES];
__device__ float g_asrc[N_NODES];
__device__ float g_adst[N_NODES];
__device__ float g_max[N_NODES];
__device__ float g_den[N_NODES];
__device__ float g_p[2 * 128];                      // p_src | p_dst

// ---------------- helpers ----------------
__device__ __forceinline__ float atomicMaxFloat(float* addr, float value) {
    // mixed-sign-safe float max
    if (value >= 0.0f)
        return __int_as_float(atomicMax((int*)addr, __float_as_int(value)));
    else
        return __uint_as_float(atomicMin((unsigned int*)addr, __float_as_uint(value)));
}

// p_src[i] = sum_c W_src[i,c]*att_src[c]; same for dst.  128 threads (K=128 both layers).
__global__ void compute_p_kernel(const float* __restrict__ Ws, const float* __restrict__ as_,
                                 const float* __restrict__ Wd, const float* __restrict__ ad_,
                                 int C) {
    int i = threadIdx.x;  // 0..127
    float s = 0.f, d = 0.f;
    for (int c = 0; c < C; c++) {
        s += Ws[i * C + c] * as_[c];
        d += Wd[i * C + c] * ad_[c];
    }
    g_p[i] = s;
    g_p[128 + i] = d;
}

// One warp per node: a_src = feat . p_src, a_dst = feat . p_dst; also (re)init max/den.
__global__ void node_av_kernel(const float* __restrict__ feat) {
    int warp = (blockIdx.x * blockDim.x + threadIdx.x) >> 5;
    int lane = threadIdx.x & 31;
    if (warp >= N_NODES) return;
    const float* f = feat + (size_t)warp * 128;
    float4 v = ((const float4*)f)[lane];
    float4 ps = ((const float4*)g_p)[lane];
    float4 pd = ((const float4*)(g_p + 128))[lane];
    float s = v.x * ps.x + v.y * ps.y + v.z * ps.z + v.w * ps.w;
    float d = v.x * pd.x + v.y * pd.y + v.z * pd.z + v.w * pd.w;
    #pragma unroll
    for (int o = 16; o > 0; o >>= 1) {
        s += __shfl_down_sync(0xffffffffu, s, o);
        d += __shfl_down_sync(0xffffffffu, d, o);
    }
    if (lane == 0) {
        g_asrc[warp] = s;
        g_adst[warp] = d;
        g_max[warp]  = -CUDART_INF_F;
        g_den[warp]  = 0.0f;
    }
}

__global__ void zero_kernel(float* __restrict__ p, int n) {
    int i = blockIdx.x * blockDim.x + threadIdx.x;
    if (i < n) p[i] = 0.0f;
}

// ---------------- GEMM: H[nrows,COUT] = X[nrows,K] @ W[K,COUT] ----------------
template<int K, int COUT>
__global__ void gemm_kernel(const float* __restrict__ X, const float* __restrict__ W,
                            float* __restrict__ H, int nrows) {
    constexpr int CPT = 4;                 // cols per thread (float4 W read)
    constexpr int RPT = 4;                 // rows per thread
    constexpr int TPR = COUT / CPT;        // threads per row-group (32 or 16)
    constexpr int GROUPS = 256 / TPR;      // row-groups per block
    constexpr int ROWS = GROUPS * RPT;     // rows per block (32 or 64)
    constexpr int KTILE = 64;
    constexpr int XS_STRIDE = KTILE + 1;

    __shared__ float Ws[KTILE * COUT];
    __shared__ float Xs[ROWS * XS_STRIDE];

    int tid = threadIdx.x;
    int grp = tid / TPR;
    int c0  = (tid % TPR) * CPT;
    int r0  = grp * RPT;
    long long row0 = (long long)blockIdx.x * ROWS;

    float acc[RPT][CPT];
    #pragma unroll
    for (int r = 0; r < RPT; r++)
        #pragma unroll
        for (int c = 0; c < CPT; c++) acc[r][c] = 0.0f;

    for (int kp = 0; kp < K; kp += KTILE) {
        for (int i = tid; i < KTILE * COUT; i += 256)
            Ws[i] = W[(size_t)(kp + i / COUT) * COUT + (i % COUT)];
        for (int i = tid; i < ROWS * KTILE; i += 256) {
            int rr = i / KTILE, kk = i % KTILE;
            long long grow = row0 + rr;
            Xs[rr * XS_STRIDE + kk] = (grow < nrows) ? X[grow * K + kp + kk] : 0.0f;
        }
        __syncthreads();
        #pragma unroll 8
        for (int k = 0; k < KTILE; k++) {
            float4 wv = *(const float4*)&Ws[k * COUT + c0];
            #pragma unroll
            for (int r = 0; r < RPT; r++) {
                float xv = Xs[(r0 + r) * XS_STRIDE + k];
                acc[r][0] += xv * wv.x;
                acc[r][1] += xv * wv.y;
                acc[r][2] += xv * wv.z;
                acc[r][3] += xv * wv.w;
            }
        }
        __syncthreads();
    }
    #pragma unroll
    for (int r = 0; r < RPT; r++) {
        long long grow = row0 + r0 + r;
        if (grow < nrows) {
            float* o = H + grow * COUT + c0;
            o[0] = acc[r][0]; o[1] = acc[r][1]; o[2] = acc[r][2]; o[3] = acc[r][3];
        }
    }
}

// ---------------- edge pass A: leaky-relu logits + segment max ----------------
__global__ void edge_logits_kernel(const int* __restrict__ src,
                                   const int* __restrict__ dst) {
    int e = blockIdx.x * blockDim.x + threadIdx.x;
    if (e >= N_EDGES) return;
    int s = src[e];
    int d = dst[e];
    if ((unsigned)s >= N_NODES || (unsigned)d >= N_NODES) return;  // dtype-guard
    float l = g_asrc[s] + g_adst[d];
    l = (l > 0.0f) ? l : NEG_SLOPE * l;
    g_logit[e] = l;
    atomicMaxFloat(&g_max[d], l);
}

// ---------------- edge pass B: e = exp(l - max); den += e; acc[dst] += e*h[src] ----
template<int C>
__global__ void edge_aggregate_kernel(const int* __restrict__ src,
                                      const int* __restrict__ dst,
                                      const float* __restrict__ h,
                                      float* __restrict__ acc) {
    int gw = blockIdx.x * (blockDim.x >> 5) + (threadIdx.x >> 5);
    if (gw >= N_EDGES) return;
    int lane = threadIdx.x & 31;
    int s = src[gw];
    int d = dst[gw];
    if ((unsigned)s >= N_NODES || (unsigned)d >= N_NODES) return;  // dtype-guard
    float ev = __expf(g_logit[gw] - g_max[d]);
    if (lane == 0) atomicAdd(&g_den[d], ev);
    const float* hp = h + (size_t)s * C;
    float* ap = acc + (size_t)d * C;
    if (C == 128) {
        float4 v = ((const float4*)hp)[lane];
        atomicAdd(ap + 4 * lane + 0, ev * v.x);
        atomicAdd(ap + 4 * lane + 1, ev * v.y);
        atomicAdd(ap + 4 * lane + 2, ev * v.z);
        atomicAdd(ap + 4 * lane + 3, ev * v.w);
    } else {
        float2 v = ((const float2*)hp)[lane];
        atomicAdd(ap + 2 * lane + 0, ev * v.x);
        atomicAdd(ap + 2 * lane + 1, ev * v.y);
    }
}

// ---------------- node epilogue: acc = [relu](acc/(den+eps) + bias) -------------
template<int C, bool RELU>
__global__ void finalize_kernel(float* __restrict__ acc, const float* __restrict__ bias) {
    int i = blockIdx.x * blockDim.x + threadIdx.x;
    if (i >= N_NODES * C) return;
    int n = i / C;
    int c = i - n * C;
    float v = acc[i] / (g_den[n] + 1e-16f) + bias[c];
    if (RELU) v = fmaxf(v, 0.0f);
    acc[i] = v;
}

// ---------------- launch ----------------
extern "C" void kernel_launch(void* const* d_in, const int* in_sizes, int n_in,
                              void* d_out, int out_size) {
    const float* x   = (const float*)d_in[0];
    const int*   ei  = (const int*)d_in[1];      // edge_index: int32 (JAX x64 disabled)
    const float* W1s = (const float*)d_in[2];
    const float* a1s = (const float*)d_in[4];
    const float* W1d = (const float*)d_in[3];
    const float* a1d = (const float*)d_in[5];
    const float* b1  = (const float*)d_in[6];
    const float* W2s = (const float*)d_in[7];
    const float* W2d = (const float*)d_in[8];
    const float* a2s = (const float*)d_in[9];
    const float* a2d = (const float*)d_in[10];
    const float* b2  = (const float*)d_in[11];
    float* out = (float*)d_out;

    const int* srcp = ei;             // edge_index[0]
    const int* dstp = ei + N_EDGES;   // edge_index[1]

    void *p_h1, *p_acc, *p_h2;
    cudaGetSymbolAddress(&p_h1, g_h1);
    cudaGetSymbolAddress(&p_acc, g_acc);
    cudaGetSymbolAddress(&p_h2, g_h2);
    float* h1  = (float*)p_h1;
    float* acc = (float*)p_acc;
    float* h2  = (float*)p_h2;

    const int TB = 256;
    const int nodeWarpBlocks = (N_NODES * 32 + TB - 1) / TB;
    const int edgeBlocks     = (N_EDGES + TB - 1) / TB;
    const int edgeWarpBlocks = (N_EDGES / (TB / 32)) + 1;

    // ---------------- layer 1 ----------------
    compute_p_kernel<<<1, 128>>>(W1s, a1s, W1d, a1d, DIM_HID);
    node_av_kernel<<<nodeWarpBlocks, TB>>>(x);
    gemm_kernel<DIM_IN, DIM_HID><<<(N_NODES + 31) / 32, TB>>>(x, W1s, h1, N_NODES);
    zero_kernel<<<(N_NODES * DIM_HID + TB - 1) / TB, TB>>>(acc, N_NODES * DIM_HID);
    edge_logits_kernel<<<edgeBlocks, TB>>>(srcp, dstp);
    edge_aggregate_kernel<DIM_HID><<<edgeWarpBlocks, TB>>>(srcp, dstp, h1, acc);
    finalize_kernel<DIM_HID, true><<<(N_NODES * DIM_HID + TB - 1) / TB, TB>>>(acc, b1);

    // ---------------- layer 2 ----------------
    compute_p_kernel<<<1, 128>>>(W2s, a2s, W2d, a2d, DIM_OUT);
    node_av_kernel<<<nodeWarpBlocks, TB>>>(acc);
    gemm_kernel<DIM_HID, DIM_OUT><<<(N_NODES + 63) / 64, TB>>>(acc, W2s, h2, N_NODES);
    zero_kernel<<<(N_NODES * DIM_OUT + TB - 1) / TB, TB>>>(out, N_NODES * DIM_OUT);
    edge_logits_kernel<<<edgeBlocks, TB>>>(srcp, dstp);
    edge_aggregate_kernel<DIM_OUT><<<edgeWarpBlocks, TB>>>(srcp, dstp, h2, out);
    finalize_kernel<DIM_OUT, false><<<(N_NODES * DIM_OUT + TB - 1) / TB, TB>>>(out, b2);

    (void)in_sizes; (void)n_in; (void)out_size;
}

// round 3
// speedup vs baseline: 2.4577x; 2.4577x over previous
#include <cuda_runtime.h>
#include <math_constants.h>

// ---------------- problem constants ----------------
#define N_NODES 100000
#define N_EDGES 1600000
#define DIM_IN  128
#define DIM_HID 128
#define DIM_OUT 64
#define NEG_SLOPE 0.2f

#define SCAN_BLK 1024
#define N_SCAN_BLOCKS ((N_NODES + SCAN_BLK - 1) / SCAN_BLK)   // 98

// ---------------- scratch (device globals; no allocation allowed) ----------
__device__ float g_h1[(size_t)N_NODES * DIM_HID];   // x @ W1_src
__device__ float g_acc[(size_t)N_NODES * DIM_HID];  // layer1 output h
__device__ float g_h2[(size_t)N_NODES * DIM_OUT];   // h @ W2_src
__device__ float g_asrc[N_NODES];
__device__ float g_adst[N_NODES];
__device__ float g_p[2 * 128];                      // p_src | p_dst

// CSR scratch
__device__ int g_cnt[N_NODES];
__device__ int g_incl[N_NODES];                     // per-block inclusive scan of cnt
__device__ int g_bsum[N_SCAN_BLOCKS];               // block totals
__device__ int g_boff[N_SCAN_BLOCKS];               // exclusive prefix of block totals
__device__ int g_rowptr[N_NODES + 1];
__device__ int g_woff[N_NODES];                     // running write offsets for scatter
__device__ int g_csr_src[N_EDGES];

// ---------------- CSR build ----------------
__global__ void hist_kernel(const int* __restrict__ dst) {
    int e = blockIdx.x * blockDim.x + threadIdx.x;
    if (e >= N_EDGES) return;
    int d = dst[e];
    if ((unsigned)d < N_NODES) atomicAdd(&g_cnt[d], 1);
}

// per-block inclusive scan (Hillis-Steele over 1024)
__global__ void scan1_kernel() {
    __shared__ int s[SCAN_BLK];
    int tid = threadIdx.x;
    int i = blockIdx.x * SCAN_BLK + tid;
    s[tid] = (i < N_NODES) ? g_cnt[i] : 0;
    __syncthreads();
    #pragma unroll
    for (int off = 1; off < SCAN_BLK; off <<= 1) {
        int v = (tid >= off) ? s[tid - off] : 0;
        __syncthreads();
        s[tid] += v;
        __syncthreads();
    }
    if (i < N_NODES) g_incl[i] = s[tid];
    if (tid == SCAN_BLK - 1) g_bsum[blockIdx.x] = s[tid];
}

// single-block scan of the 98 block sums -> exclusive offsets
__global__ void scan2_kernel() {
    __shared__ int s[128];
    int tid = threadIdx.x;  // 128 threads
    int v0 = (tid < N_SCAN_BLOCKS) ? g_bsum[tid] : 0;
    s[tid] = v0;
    __syncthreads();
    #pragma unroll
    for (int off = 1; off < 128; off <<= 1) {
        int v = (tid >= off) ? s[tid - off] : 0;
        __syncthreads();
        s[tid] += v;
        __syncthreads();
    }
    if (tid < N_SCAN_BLOCKS) g_boff[tid] = s[tid] - v0;  // exclusive
}

// rowptr[i] = exclusive scan; also init write offsets
__global__ void scan3_kernel() {
    int i = blockIdx.x * blockDim.x + threadIdx.x;
    if (i >= N_NODES) return;
    int excl = g_incl[i] - g_cnt[i] + g_boff[i / SCAN_BLK];
    g_rowptr[i] = excl;
    g_woff[i]   = excl;
    if (i == 0) g_rowptr[N_NODES] = N_EDGES;
}

__global__ void scatter_kernel(const int* __restrict__ src, const int* __restrict__ dst) {
    int e = blockIdx.x * blockDim.x + threadIdx.x;
    if (e >= N_EDGES) return;
    int s = src[e];
    int d = dst[e];
    if ((unsigned)s >= N_NODES || (unsigned)d >= N_NODES) return;
    int pos = atomicAdd(&g_woff[d], 1);
    g_csr_src[pos] = s;
}

// ---------------- per-layer node prep ----------------
// p_src[i] = sum_c W_src[i,c]*att_src[c]; same for dst. 128 threads (K=128 both layers).
__global__ void compute_p_kernel(const float* __restrict__ Ws, const float* __restrict__ as_,
                                 const float* __restrict__ Wd, const float* __restrict__ ad_,
                                 int C) {
    int i = threadIdx.x;  // 0..127
    float s = 0.f, d = 0.f;
    for (int c = 0; c < C; c++) {
        s += Ws[i * C + c] * as_[c];
        d += Wd[i * C + c] * ad_[c];
    }
    g_p[i] = s;
    g_p[128 + i] = d;
}

// One warp per node: a_src = feat . p_src, a_dst = feat . p_dst.
__global__ void node_av_kernel(const float* __restrict__ feat) {
    int warp = (blockIdx.x * blockDim.x + threadIdx.x) >> 5;
    int lane = threadIdx.x & 31;
    if (warp >= N_NODES) return;
    const float* f = feat + (size_t)warp * 128;
    float4 v = ((const float4*)f)[lane];
    float4 ps = ((const float4*)g_p)[lane];
    float4 pd = ((const float4*)(g_p + 128))[lane];
    float s = v.x * ps.x + v.y * ps.y + v.z * ps.z + v.w * ps.w;
    float d = v.x * pd.x + v.y * pd.y + v.z * pd.z + v.w * pd.w;
    #pragma unroll
    for (int o = 16; o > 0; o >>= 1) {
        s += __shfl_down_sync(0xffffffffu, s, o);
        d += __shfl_down_sync(0xffffffffu, d, o);
    }
    if (lane == 0) {
        g_asrc[warp] = s;
        g_adst[warp] = d;
    }
}

// ---------------- GEMM: H[nrows,COUT] = X[nrows,K] @ W[K,COUT] ----------------
template<int K, int COUT>
__global__ void gemm_kernel(const float* __restrict__ X, const float* __restrict__ W,
                            float* __restrict__ H, int nrows) {
    constexpr int CPT = 4;
    constexpr int RPT = 4;
    constexpr int TPR = COUT / CPT;
    constexpr int GROUPS = 256 / TPR;
    constexpr int ROWS = GROUPS * RPT;
    constexpr int KTILE = 64;
    constexpr int XS_STRIDE = KTILE + 1;

    __shared__ float Ws[KTILE * COUT];
    __shared__ float Xs[ROWS * XS_STRIDE];

    int tid = threadIdx.x;
    int grp = tid / TPR;
    int c0  = (tid % TPR) * CPT;
    int r0  = grp * RPT;
    long long row0 = (long long)blockIdx.x * ROWS;

    float acc[RPT][CPT];
    #pragma unroll
    for (int r = 0; r < RPT; r++)
        #pragma unroll
        for (int c = 0; c < CPT; c++) acc[r][c] = 0.0f;

    for (int kp = 0; kp < K; kp += KTILE) {
        for (int i = tid; i < KTILE * COUT; i += 256)
            Ws[i] = W[(size_t)(kp + i / COUT) * COUT + (i % COUT)];
        for (int i = tid; i < ROWS * KTILE; i += 256) {
            int rr = i / KTILE, kk = i % KTILE;
            long long grow = row0 + rr;
            Xs[rr * XS_STRIDE + kk] = (grow < nrows) ? X[grow * K + kp + kk] : 0.0f;
        }
        __syncthreads();
        #pragma unroll 8
        for (int k = 0; k < KTILE; k++) {
            float4 wv = *(const float4*)&Ws[k * COUT + c0];
            #pragma unroll
            for (int r = 0; r < RPT; r++) {
                float xv = Xs[(r0 + r) * XS_STRIDE + k];
                acc[r][0] += xv * wv.x;
                acc[r][1] += xv * wv.y;
                acc[r][2] += xv * wv.z;
                acc[r][3] += xv * wv.w;
            }
        }
        __syncthreads();
    }
    #pragma unroll
    for (int r = 0; r < RPT; r++) {
        long long grow = row0 + r0 + r;
        if (grow < nrows) {
            float* o = H + grow * COUT + c0;
            o[0] = acc[r][0]; o[1] = acc[r][1]; o[2] = acc[r][2]; o[3] = acc[r][3];
        }
    }
}

// ---------------- fused softmax + aggregate + bias (+relu), warp per dst node ----
#define LCACHE 128
template<int C, bool RELU>
__global__ void node_aggregate_kernel(const float* __restrict__ h,
                                      const float* __restrict__ bias,
                                      float* __restrict__ out) {
    __shared__ float lc[8][LCACHE];           // 8 warps/block
    int warp = (blockIdx.x * blockDim.x + threadIdx.x) >> 5;
    int w    = (threadIdx.x >> 5);
    int lane = threadIdx.x & 31;
    if (warp >= N_NODES) return;
    int n   = warp;
    int beg = g_rowptr[n];
    int end = g_rowptr[n + 1];
    float ad = g_adst[n];

    // pass 1: logits -> lcache, running max
    float m = -CUDART_INF_F;
    for (int i = beg + lane; i < end; i += 32) {
        int s = g_csr_src[i];
        float l = g_asrc[s] + ad;
        l = (l > 0.0f) ? l : NEG_SLOPE * l;
        int off = i - beg;
        if (off < LCACHE) lc[w][off] = l;
        m = fmaxf(m, l);
    }
    #pragma unroll
    for (int o = 16; o > 0; o >>= 1)
        m = fmaxf(m, __shfl_xor_sync(0xffffffffu, m, o));
    __syncwarp();

    // pass 2: sequential over edges; whole warp gathers one h row per step
    float den = 0.0f;
    float a0 = 0.f, a1 = 0.f, a2 = 0.f, a3 = 0.f;
    for (int i = beg; i < end; i++) {
        int off = i - beg;
        float l;
        if (off < LCACHE) {
            l = lc[w][off];
        } else {
            int s2 = g_csr_src[i];
            l = g_asrc[s2] + ad;
            l = (l > 0.0f) ? l : NEG_SLOPE * l;
        }
        float ev = __expf(l - m);
        den += ev;                               // identical in all lanes
        int s = g_csr_src[i];                    // broadcast load
        if (C == 128) {
            float4 v = ((const float4*)(h + (size_t)s * C))[lane];
            a0 += ev * v.x; a1 += ev * v.y; a2 += ev * v.z; a3 += ev * v.w;
        } else {
            float2 v = ((const float2*)(h + (size_t)s * C))[lane];
            a0 += ev * v.x; a1 += ev * v.y;
        }
    }

    float inv = 1.0f / (den + 1e-16f);
    if (C == 128) {
        float4 b = ((const float4*)bias)[lane];
        float4 r;
        r.x = a0 * inv + b.x; r.y = a1 * inv + b.y;
        r.z = a2 * inv + b.z; r.w = a3 * inv + b.w;
        if (RELU) {
            r.x = fmaxf(r.x, 0.f); r.y = fmaxf(r.y, 0.f);
            r.z = fmaxf(r.z, 0.f); r.w = fmaxf(r.w, 0.f);
        }
        ((float4*)(out + (size_t)n * C))[lane] = r;
    } else {
        float2 b = ((const float2*)bias)[lane];
        float2 r;
        r.x = a0 * inv + b.x; r.y = a1 * inv + b.y;
        if (RELU) { r.x = fmaxf(r.x, 0.f); r.y = fmaxf(r.y, 0.f); }
        ((float2*)(out + (size_t)n * C))[lane] = r;
    }
}

// ---------------- launch ----------------
extern "C" void kernel_launch(void* const* d_in, const int* in_sizes, int n_in,
                              void* d_out, int out_size) {
    const float* x   = (const float*)d_in[0];
    const int*   ei  = (const int*)d_in[1];      // int32 (JAX x64 disabled)
    const float* W1s = (const float*)d_in[2];
    const float* W1d = (const float*)d_in[3];
    const float* a1s = (const float*)d_in[4];
    const float* a1d = (const float*)d_in[5];
    const float* b1  = (const float*)d_in[6];
    const float* W2s = (const float*)d_in[7];
    const float* W2d = (const float*)d_in[8];
    const float* a2s = (const float*)d_in[9];
    const float* a2d = (const float*)d_in[10];
    const float* b2  = (const float*)d_in[11];
    float* out = (float*)d_out;

    const int* srcp = ei;
    const int* dstp = ei + N_EDGES;

    void *p_h1, *p_acc, *p_h2, *p_cnt;
    cudaGetSymbolAddress(&p_h1, g_h1);
    cudaGetSymbolAddress(&p_acc, g_acc);
    cudaGetSymbolAddress(&p_h2, g_h2);
    cudaGetSymbolAddress(&p_cnt, g_cnt);
    float* h1  = (float*)p_h1;
    float* acc = (float*)p_acc;
    float* h2  = (float*)p_h2;

    const int TB = 256;
    const int edgeBlocks     = (N_EDGES + TB - 1) / TB;
    const int nodeBlocks     = (N_NODES + TB - 1) / TB;
    const int nodeWarpBlocks = (N_NODES * 32 + TB - 1) / TB;

    // ---------- CSR build (shared by both layers) ----------
    cudaMemsetAsync(p_cnt, 0, N_NODES * sizeof(int));
    hist_kernel<<<edgeBlocks, TB>>>(dstp);
    scan1_kernel<<<N_SCAN_BLOCKS, SCAN_BLK>>>();
    scan2_kernel<<<1, 128>>>();
    scan3_kernel<<<nodeBlocks, TB>>>();
    scatter_kernel<<<edgeBlocks, TB>>>(srcp, dstp);

    // ---------------- layer 1 ----------------
    compute_p_kernel<<<1, 128>>>(W1s, a1s, W1d, a1d, DIM_HID);
    node_av_kernel<<<nodeWarpBlocks, TB>>>(x);
    gemm_kernel<DIM_IN, DIM_HID><<<(N_NODES + 31) / 32, TB>>>(x, W1s, h1, N_NODES);
    node_aggregate_kernel<DIM_HID, true><<<nodeWarpBlocks, TB>>>(h1, b1, acc);

    // ---------------- layer 2 ----------------
    compute_p_kernel<<<1, 128>>>(W2s, a2s, W2d, a2d, DIM_OUT);
    node_av_kernel<<<nodeWarpBlocks, TB>>>(acc);
    gemm_kernel<DIM_HID, DIM_OUT><<<(N_NODES + 63) / 64, TB>>>(acc, W2s, h2, N_NODES);
    node_aggregate_kernel<DIM_OUT, false><<<nodeWarpBlocks, TB>>>(h2, b2, out);

    (void)in_sizes; (void)n_in; (void)out_size;
}